// round 3
// baseline (speedup 1.0000x reference)
#include <cuda_runtime.h>
#include <cstdint>
#include <cstddef>

typedef unsigned long long ull;

#define B_    2048
#define T_    200
#define H1_   80
#define H2_   40
#define NROWS (B_*T_)        // 409600
#define NB1   (NROWS/256)    // 1600
#define NB2   (NROWS/512)    // 800
#define PADV  (-4294967296.0f)

// ---------------- device scratch ----------------
__device__ float g_h1[(size_t)NROWS*H1_];     // 131 MB
__device__ float g_h2[(size_t)NROWS*H2_];     // 65.5 MB
__device__ float g_Wc[128*H1_];
__device__ float g_qb[B_*H1_];
__device__ float g_part1[NB1*2*H1_];
__device__ float g_part2[NB2*2*H2_];
__device__ float g_m1[H1_], g_r1[H1_];
__device__ float g_m2[H2_], g_r2[H2_];
__device__ int   g_mask_mode;                 // 0=u8, 1=i32, 2=f32

// ---------------- f32x2 helpers ----------------
__device__ __forceinline__ ull dup2(float v) {
    ull r;
    asm("mov.b64 %0, {%1, %1};" : "=l"(r) : "f"(v));
    return r;
}
__device__ __forceinline__ void fma2(ull& acc, ull a, ull b) {
    asm("fma.rn.f32x2 %0, %1, %2, %0;" : "+l"(acc) : "l"(a), "l"(b));
}
__device__ __forceinline__ void unpk(ull v, float& lo, float& hi) {
    asm("mov.b64 {%0, %1}, %2;" : "=f"(lo), "=f"(hi) : "l"(v));
}
// 128-bit shared load straight into two 64-bit (f32x2) regs
__device__ __forceinline__ void lds128u(uint32_t saddr, ull& a, ull& b) {
    asm volatile("ld.shared.v2.u64 {%0, %1}, [%2];"
                 : "=l"(a), "=l"(b) : "r"(saddr));
}

// ---------------- mask dtype detection ----------------
__global__ void detect_mask(const unsigned char* __restrict__ m) {
    __shared__ int s_f32ok, s_i32ok, s_f32one, s_i32one;
    if (threadIdx.x == 0) { s_f32ok = 1; s_i32ok = 1; s_f32one = 0; s_i32one = 0; }
    __syncthreads();
    const unsigned* w = (const unsigned*)m;
    int f32ok = 1, i32ok = 1, f32one = 0, i32one = 0;
    for (int i = threadIdx.x; i < 1024; i += 256) {
        unsigned v = w[i];
        if (v != 0u && v != 0x3F800000u) f32ok = 0;
        if (v == 0x3F800000u) f32one = 1;
        if (v != 0u && v != 1u) i32ok = 0;
        if (v == 1u) i32one = 1;
    }
    if (!f32ok) atomicAnd(&s_f32ok, 0);
    if (f32one) atomicOr(&s_f32one, 1);
    if (!i32ok) atomicAnd(&s_i32ok, 0);
    if (i32one) atomicOr(&s_i32one, 1);
    __syncthreads();
    if (threadIdx.x == 0) {
        int mode = 0;
        if (s_f32ok && s_f32one)      mode = 2;
        else if (s_i32ok && s_i32one) mode = 1;
        g_mask_mode = mode;
    }
}

// ---------------- prep kernels ----------------
__global__ void prep_wc(const float* __restrict__ W1) {
    int i = blockIdx.x * blockDim.x + threadIdx.x;
    if (i >= 128 * H1_) return;
    int d = i / H1_, h = i - d * H1_;
    float v;
    if (d < 64) v = W1[(64 + d) * H1_ + h] - W1[(128 + d) * H1_ + h];
    else        v = W1[(128 + d) * H1_ + h];
    g_Wc[i] = v;
}

__global__ void prep_qb(const float* __restrict__ queries,
                        const float* __restrict__ W1,
                        const float* __restrict__ b1) {
    __shared__ float qs[64];
    int b = blockIdx.x, tid = threadIdx.x;
    if (tid < 64) qs[tid] = queries[b * 64 + tid];
    __syncthreads();
    if (tid < H1_) {
        float acc = b1[tid];
        #pragma unroll 8
        for (int d = 0; d < 64; ++d)
            acc += qs[d] * (W1[d * H1_ + tid] + W1[(128 + d) * H1_ + tid]);
        g_qb[b * H1_ + tid] = acc;
    }
}

// ---------------- K1: 256-row tile, 4x20 per thread, f32x2 ----------------
__global__ void __launch_bounds__(256, 1)
k1(const float* __restrict__ keys, const float* __restrict__ queries) {
    extern __shared__ float sm[];
    float* As = sm;                    // [256][132]
    float* Ws = sm + 256 * 132;        // [128][80]
    int tid = threadIdx.x;
    int row0 = blockIdx.x * 256;

    for (int i = tid; i < 128 * H1_; i += 256) Ws[i] = g_Wc[i];
    for (int i = tid; i < 256 * 64; i += 256) {
        int r = i >> 6, d = i & 63;
        int row = row0 + r;
        float kv = keys[(size_t)row * 64 + d];
        float qv = queries[(row / T_) * 64 + d];
        As[r * 132 + d]      = kv;
        As[r * 132 + 64 + d] = kv * qv;
    }
    __syncthreads();

    int tx = tid & 3, ty = tid >> 2;   // 4 col-groups of 20, 64 row-groups
    int col0 = tx * 20;
    ull acc[4][10];
    #pragma unroll
    for (int r = 0; r < 4; ++r)
        #pragma unroll
        for (int j = 0; j < 10; ++j) acc[r][j] = 0ull;

    uint32_t wbase = (uint32_t)__cvta_generic_to_shared(Ws) + col0 * 4;
    const float* ap = As + ty * 132;

    #pragma unroll 1
    for (int d = 0; d < 128; d += 4) {
        float4 a0 = *(const float4*)(ap + d);
        float4 a1 = *(const float4*)(ap + 64 * 132 + d);
        float4 a2 = *(const float4*)(ap + 128 * 132 + d);
        float4 a3 = *(const float4*)(ap + 192 * 132 + d);
        #pragma unroll
        for (int dd = 0; dd < 4; ++dd) {
            uint32_t wa = wbase + (d + dd) * 320;
            ull w[10];
            lds128u(wa,      w[0], w[1]);
            lds128u(wa + 16, w[2], w[3]);
            lds128u(wa + 32, w[4], w[5]);
            lds128u(wa + 48, w[6], w[7]);
            lds128u(wa + 64, w[8], w[9]);
            float f0 = (dd == 0) ? a0.x : (dd == 1) ? a0.y : (dd == 2) ? a0.z : a0.w;
            float f1 = (dd == 0) ? a1.x : (dd == 1) ? a1.y : (dd == 2) ? a1.z : a1.w;
            float f2 = (dd == 0) ? a2.x : (dd == 1) ? a2.y : (dd == 2) ? a2.z : a2.w;
            float f3 = (dd == 0) ? a3.x : (dd == 1) ? a3.y : (dd == 2) ? a3.z : a3.w;
            ull av[4];
            av[0] = dup2(f0); av[1] = dup2(f1); av[2] = dup2(f2); av[3] = dup2(f3);
            #pragma unroll
            for (int r = 0; r < 4; ++r)
                #pragma unroll
                for (int j = 0; j < 10; ++j)
                    fma2(acc[r][j], av[r], w[j]);
        }
    }

    float s[20], ss[20];
    #pragma unroll
    for (int j = 0; j < 20; ++j) { s[j] = 0.f; ss[j] = 0.f; }

    #pragma unroll
    for (int r = 0; r < 4; ++r) {
        int row = row0 + ty + 64 * r;
        const float4* qbp = (const float4*)(g_qb + (row / T_) * H1_ + col0);
        float4* op = (float4*)(g_h1 + (size_t)row * H1_ + col0);
        #pragma unroll
        for (int j = 0; j < 5; ++j) {
            float4 q = qbp[j];
            float v0, v1, v2, v3;
            unpk(acc[r][2 * j],     v0, v1);
            unpk(acc[r][2 * j + 1], v2, v3);
            v0 += q.x; v1 += q.y; v2 += q.z; v3 += q.w;
            float4 o; o.x = v0; o.y = v1; o.z = v2; o.w = v3;
            op[j] = o;
            s[4 * j + 0] += v0; ss[4 * j + 0] += v0 * v0;
            s[4 * j + 1] += v1; ss[4 * j + 1] += v1 * v1;
            s[4 * j + 2] += v2; ss[4 * j + 2] += v2 * v2;
            s[4 * j + 3] += v3; ss[4 * j + 3] += v3 * v3;
        }
    }

    __syncthreads();
    float* reds  = sm;                 // [64][80]
    float* redss = sm + 64 * H1_;
    #pragma unroll
    for (int j = 0; j < 20; ++j) {
        reds[ty * H1_ + col0 + j]  = s[j];
        redss[ty * H1_ + col0 + j] = ss[j];
    }
    __syncthreads();
    if (tid < H1_) {
        float S = 0.f, SS = 0.f;
        #pragma unroll 8
        for (int i = 0; i < 64; ++i) {
            S  += reds[i * H1_ + tid];
            SS += redss[i * H1_ + tid];
        }
        g_part1[blockIdx.x * (2 * H1_) + tid]       = S;
        g_part1[blockIdx.x * (2 * H1_) + H1_ + tid] = SS;
    }
}

// ---------------- stats ----------------
__global__ void stats1() {
    __shared__ float rs[256], rss[256];
    int h = blockIdx.x, tid = threadIdx.x;
    float S = 0.f, SS = 0.f;
    for (int k = tid; k < NB1; k += 256) {
        S  += g_part1[k * (2 * H1_) + h];
        SS += g_part1[k * (2 * H1_) + H1_ + h];
    }
    rs[tid] = S; rss[tid] = SS;
    __syncthreads();
    for (int st = 128; st > 0; st >>= 1) {
        if (tid < st) { rs[tid] += rs[tid + st]; rss[tid] += rss[tid + st]; }
        __syncthreads();
    }
    if (tid == 0) {
        float mean = rs[0] / (float)NROWS;
        float var  = rss[0] / (float)NROWS - mean * mean;
        g_m1[h] = mean;
        g_r1[h] = rsqrtf(fmaxf(var, 0.f) + 1e-8f);
    }
}

__global__ void stats2() {
    __shared__ float rs[256], rss[256];
    int h = blockIdx.x, tid = threadIdx.x;
    float S = 0.f, SS = 0.f;
    for (int k = tid; k < NB2; k += 256) {
        S  += g_part2[k * (2 * H2_) + h];
        SS += g_part2[k * (2 * H2_) + H2_ + h];
    }
    rs[tid] = S; rss[tid] = SS;
    __syncthreads();
    for (int st = 128; st > 0; st >>= 1) {
        if (tid < st) { rs[tid] += rs[tid + st]; rss[tid] += rss[tid + st]; }
        __syncthreads();
    }
    if (tid == 0) {
        float mean = rs[0] / (float)NROWS;
        float var  = rss[0] / (float)NROWS - mean * mean;
        g_m2[h] = mean;
        g_r2[h] = rsqrtf(fmaxf(var, 0.f) + 1e-8f);
    }
}

// ---------------- K2: 512-row tile, dice + GEMM, f32x2 ----------------
__global__ void __launch_bounds__(256, 1)
k2(const float* __restrict__ W2, const float* __restrict__ b2,
   const float* __restrict__ a1) {
    extern __shared__ float sm[];
    float* A2  = sm;                   // [512][84]
    float* W2s = sm + 512 * 84;        // [80][40]
    __shared__ float pm[H1_], pr[H1_], pa[H1_];
    int tid = threadIdx.x;
    int row0 = blockIdx.x * 512;

    if (tid < H1_) { pm[tid] = g_m1[tid]; pr[tid] = g_r1[tid]; pa[tid] = a1[tid]; }
    for (int i = tid; i < H1_ * H2_; i += 256) W2s[i] = W2[i];
    __syncthreads();

    for (int i = tid; i < 512 * H1_; i += 256) {
        int r = i / H1_, c = i - r * H1_;
        float x  = g_h1[(size_t)row0 * H1_ + i];
        float xn = (x - pm[c]) * pr[c];
        float p  = 1.f / (1.f + __expf(-xn));
        float al = pa[c];
        A2[r * 84 + c] = x * (al + p * (1.f - al));
    }
    __syncthreads();

    int tx = tid & 1, ty = tid >> 1;   // 2 col-groups of 20, 128 row-groups
    int col0 = tx * 20;
    ull acc[4][10];
    #pragma unroll
    for (int r = 0; r < 4; ++r)
        #pragma unroll
        for (int j = 0; j < 10; ++j) acc[r][j] = 0ull;

    uint32_t wbase = (uint32_t)__cvta_generic_to_shared(W2s) + col0 * 4;
    const float* ap = A2 + ty * 84;

    #pragma unroll 1
    for (int d = 0; d < H1_; d += 4) {
        float4 a0 = *(const float4*)(ap + d);
        float4 a1v = *(const float4*)(ap + 128 * 84 + d);
        float4 a2v = *(const float4*)(ap + 256 * 84 + d);
        float4 a3v = *(const float4*)(ap + 384 * 84 + d);
        #pragma unroll
        for (int dd = 0; dd < 4; ++dd) {
            uint32_t wa = wbase + (d + dd) * 160;
            ull w[10];
            lds128u(wa,      w[0], w[1]);
            lds128u(wa + 16, w[2], w[3]);
            lds128u(wa + 32, w[4], w[5]);
            lds128u(wa + 48, w[6], w[7]);
            lds128u(wa + 64, w[8], w[9]);
            float f0 = (dd == 0) ? a0.x  : (dd == 1) ? a0.y  : (dd == 2) ? a0.z  : a0.w;
            float f1 = (dd == 0) ? a1v.x : (dd == 1) ? a1v.y : (dd == 2) ? a1v.z : a1v.w;
            float f2 = (dd == 0) ? a2v.x : (dd == 1) ? a2v.y : (dd == 2) ? a2v.z : a2v.w;
            float f3 = (dd == 0) ? a3v.x : (dd == 1) ? a3v.y : (dd == 2) ? a3v.z : a3v.w;
            ull av[4];
            av[0] = dup2(f0); av[1] = dup2(f1); av[2] = dup2(f2); av[3] = dup2(f3);
            #pragma unroll
            for (int r = 0; r < 4; ++r)
                #pragma unroll
                for (int j = 0; j < 10; ++j)
                    fma2(acc[r][j], av[r], w[j]);
        }
    }

    float s[20], ss[20];
    #pragma unroll
    for (int j = 0; j < 20; ++j) { s[j] = 0.f; ss[j] = 0.f; }

    const float4* bp = (const float4*)(b2 + col0);
    float4 bv[5];
    #pragma unroll
    for (int j = 0; j < 5; ++j) bv[j] = bp[j];

    #pragma unroll
    for (int r = 0; r < 4; ++r) {
        int row = row0 + ty + 128 * r;
        float4* op = (float4*)(g_h2 + (size_t)row * H2_ + col0);
        #pragma unroll
        for (int j = 0; j < 5; ++j) {
            float v0, v1, v2, v3;
            unpk(acc[r][2 * j],     v0, v1);
            unpk(acc[r][2 * j + 1], v2, v3);
            v0 += bv[j].x; v1 += bv[j].y; v2 += bv[j].z; v3 += bv[j].w;
            float4 o; o.x = v0; o.y = v1; o.z = v2; o.w = v3;
            op[j] = o;
            s[4 * j + 0] += v0; ss[4 * j + 0] += v0 * v0;
            s[4 * j + 1] += v1; ss[4 * j + 1] += v1 * v1;
            s[4 * j + 2] += v2; ss[4 * j + 2] += v2 * v2;
            s[4 * j + 3] += v3; ss[4 * j + 3] += v3 * v3;
        }
    }

    __syncthreads();
    float* reds  = sm;                 // [128][40]
    float* redss = sm + 128 * H2_;
    #pragma unroll
    for (int j = 0; j < 20; ++j) {
        reds[ty * H2_ + col0 + j]  = s[j];
        redss[ty * H2_ + col0 + j] = ss[j];
    }
    __syncthreads();
    if (tid < H2_) {
        float S = 0.f, SS = 0.f;
        #pragma unroll 8
        for (int i = 0; i < 128; ++i) {
            S  += reds[i * H2_ + tid];
            SS += redss[i * H2_ + tid];
        }
        g_part2[blockIdx.x * (2 * H2_) + tid]       = S;
        g_part2[blockIdx.x * (2 * H2_) + H2_ + tid] = SS;
    }
}

// ---------------- K3: scores + softmax + weighted key sum ----------------
__global__ void __launch_bounds__(256)
k3(const float* __restrict__ keys, const unsigned char* __restrict__ maskraw,
   const float* __restrict__ W3, const float* __restrict__ b3,
   const float* __restrict__ a2p, float* __restrict__ out) {
    __shared__ float sw[H2_], sm2[H2_], sr2[H2_], sa2[H2_];
    __shared__ float sc[T_];
    __shared__ float red[256];
    __shared__ float osum[256];
    int b = blockIdx.x, tid = threadIdx.x;
    int mode = g_mask_mode;

    if (tid < H2_) {
        sw[tid]  = W3[tid];
        sm2[tid] = g_m2[tid];
        sr2[tid] = g_r2[tid];
        sa2[tid] = a2p[tid];
    }
    __syncthreads();

    if (tid < T_) {
        const float* hp = g_h2 + (size_t)(b * T_ + tid) * H2_;
        float acc = b3[0];
        #pragma unroll
        for (int h = 0; h < H2_; ++h) {
            float x  = hp[h];
            float xn = (x - sm2[h]) * sr2[h];
            float p  = 1.f / (1.f + __expf(-xn));
            float al = sa2[h];
            acc += x * (al + p * (1.f - al)) * sw[h];
        }
        int idx = b * T_ + tid;
        bool mv;
        if (mode == 2)      mv = (((const float*)maskraw)[idx] != 0.0f);
        else if (mode == 1) mv = (((const int*)maskraw)[idx] != 0);
        else                mv = (maskraw[idx] != 0);
        sc[tid] = mv ? acc : PADV;
    }
    __syncthreads();

    red[tid] = (tid < T_) ? sc[tid] : -3.4e38f;
    __syncthreads();
    for (int st = 128; st > 0; st >>= 1) {
        if (tid < st) red[tid] = fmaxf(red[tid], red[tid + st]);
        __syncthreads();
    }
    float m = red[0];
    __syncthreads();

    float e = 0.f;
    if (tid < T_) e = __expf(sc[tid] - m);
    red[tid] = e;
    __syncthreads();
    for (int st = 128; st > 0; st >>= 1) {
        if (tid < st) red[tid] += red[tid + st];
        __syncthreads();
    }
    float inv = 1.0f / red[0];
    if (tid < T_) sc[tid] = e * inv;
    __syncthreads();

    int d = tid & 63, seg = tid >> 6;
    float acc2 = 0.f;
    const float* kp = keys + ((size_t)b * T_ + seg * 50) * 64 + d;
    #pragma unroll 5
    for (int t = 0; t < 50; ++t) acc2 += sc[seg * 50 + t] * kp[(size_t)t * 64];
    osum[tid] = acc2;
    __syncthreads();
    if (tid < 64)
        out[b * 64 + tid] =
            (osum[tid] + osum[64 + tid]) + (osum[128 + tid] + osum[192 + tid]);
}

// ---------------- launch ----------------
extern "C" void kernel_launch(void* const* d_in, const int* in_sizes, int n_in,
                              void* d_out, int out_size) {
    const float* queries = (const float*)d_in[0];
    const float* keys    = (const float*)d_in[1];
    const unsigned char* mask = (const unsigned char*)d_in[2];
    const float* W1 = (const float*)d_in[3];
    const float* b1 = (const float*)d_in[4];
    const float* a1 = (const float*)d_in[5];
    const float* W2 = (const float*)d_in[6];
    const float* b2 = (const float*)d_in[7];
    const float* a2 = (const float*)d_in[8];
    const float* W3 = (const float*)d_in[9];
    const float* b3 = (const float*)d_in[10];
    float* out = (float*)d_out;

    int smem1 = (256 * 132 + 128 * H1_) * 4;   // 176,128 B
    int smem2 = (512 * 84 + H1_ * H2_) * 4;    // 184,832 B
    cudaFuncSetAttribute(k1, cudaFuncAttributeMaxDynamicSharedMemorySize, smem1);
    cudaFuncSetAttribute(k2, cudaFuncAttributeMaxDynamicSharedMemorySize, smem2);

    detect_mask<<<1, 256>>>(mask);
    prep_wc<<<(128 * H1_ + 255) / 256, 256>>>(W1);
    prep_qb<<<B_, 128>>>(queries, W1, b1);
    k1<<<NB1, 256, smem1>>>(keys, queries);
    stats1<<<H1_, 256>>>();
    k2<<<NB2, 256, smem2>>>(W2, b2, a1);
    stats2<<<H2_, 256>>>();
    k3<<<B_, 256>>>(keys, mask, W3, b3, a2, out);
}

// round 5
// speedup vs baseline: 2.0961x; 2.0961x over previous
#include <cuda_runtime.h>
#include <cuda_bf16.h>
#include <cstdint>
#include <cstddef>

#define B_    2048
#define T_    200
#define H1_   80
#define H2_   40
#define NROWS (B_*T_)        // 409600
#define NT1   (NROWS/64)     // 6400 k1 tiles
#define NT2   (NROWS/128)    // 3200 k2 tiles
#define PADV  (-4294967296.0f)

// ---------------- device scratch ----------------
__device__ float g_h1[(size_t)NROWS*H1_];
__device__ float g_h2[(size_t)NROWS*H2_];
__device__ float g_qb[B_*H1_];
__device__ float g_part1[NT1*2*H1_];
__device__ float g_part2[NT2*2*H2_];
__device__ float g_m1[H1_], g_r1[H1_];
__device__ float g_m2[H2_], g_r2[H2_];
__device__ int   g_mask_mode;
// padded bf16 weight images: B1 [80][136], B2 [40][88]
__device__ __align__(16) __nv_bfloat16 g_B1h[80*136], g_B1l[80*136];
__device__ __align__(16) __nv_bfloat16 g_B2h[40*88],  g_B2l[40*88];

// ---------------- helpers ----------------
__device__ __forceinline__ uint32_t smem_u32(const void* p) {
    uint32_t a;
    asm("{ .reg .u64 t; cvta.to.shared.u64 t, %1; cvt.u32.u64 %0, t; }"
        : "=r"(a) : "l"(p));
    return a;
}
__device__ __forceinline__ uint32_t lds32(uint32_t a) {
    uint32_t v;
    asm volatile("ld.shared.b32 %0, [%1];" : "=r"(v) : "r"(a));
    return v;
}
// pack two floats into bf16x2 (x0 -> low half)
__device__ __forceinline__ uint32_t pack_bf(float x0, float x1) {
    uint32_t r;
    asm("cvt.rn.bf16x2.f32 %0, %1, %2;" : "=r"(r) : "f"(x1), "f"(x0));
    return r;
}
// store pair (k=2p, 2p+1) of row r into hi/lo bf16 images (strideW 32-bit words)
__device__ __forceinline__ void stash2(unsigned char* hi, unsigned char* lo,
                                       int strideW, int r, int p,
                                       float x0, float x1) {
    float h0 = __bfloat162float(__float2bfloat16(x0));
    float h1 = __bfloat162float(__float2bfloat16(x1));
    uint32_t off = (uint32_t)(r * strideW + p) * 4u;
    *(uint32_t*)(hi + off) = pack_bf(x0, x1);
    *(uint32_t*)(lo + off) = pack_bf(x0 - h0, x1 - h1);
}
__device__ __forceinline__ void mma_bf16(float* c,
                                         uint32_t a0, uint32_t a1, uint32_t a2, uint32_t a3,
                                         uint32_t b0, uint32_t b1) {
    asm volatile(
        "mma.sync.aligned.m16n8k16.row.col.f32.bf16.bf16.f32 "
        "{%0,%1,%2,%3}, {%4,%5,%6,%7}, {%8,%9}, {%0,%1,%2,%3};"
        : "+f"(c[0]), "+f"(c[1]), "+f"(c[2]), "+f"(c[3])
        : "r"(a0), "r"(a1), "r"(a2), "r"(a3), "r"(b0), "r"(b1));
}

// ---------------- mask dtype detection ----------------
__global__ void detect_mask(const unsigned char* __restrict__ m) {
    __shared__ int s_f32ok, s_i32ok, s_f32one, s_i32one;
    if (threadIdx.x == 0) { s_f32ok = 1; s_i32ok = 1; s_f32one = 0; s_i32one = 0; }
    __syncthreads();
    const unsigned* w = (const unsigned*)m;
    int f32ok = 1, i32ok = 1, f32one = 0, i32one = 0;
    for (int i = threadIdx.x; i < 1024; i += 256) {
        unsigned v = w[i];
        if (v != 0u && v != 0x3F800000u) f32ok = 0;
        if (v == 0x3F800000u) f32one = 1;
        if (v != 0u && v != 1u) i32ok = 0;
        if (v == 1u) i32one = 1;
    }
    if (!f32ok) atomicAnd(&s_f32ok, 0);
    if (f32one) atomicOr(&s_f32one, 1);
    if (!i32ok) atomicAnd(&s_i32ok, 0);
    if (i32one) atomicOr(&s_i32one, 1);
    __syncthreads();
    if (threadIdx.x == 0) {
        int mode = 0;
        if (s_f32ok && s_f32one)      mode = 2;
        else if (s_i32ok && s_i32one) mode = 1;
        g_mask_mode = mode;
    }
}

// ---------------- prep: weight images + qb ----------------
__global__ void prep_b1(const float* __restrict__ W1) {
    int i = blockIdx.x * blockDim.x + threadIdx.x;   // n*128 + d
    if (i >= H1_ * 128) return;
    int n = i >> 7, d = i & 127;
    float w;
    if (d < 64) w = W1[(64 + d) * H1_ + n] - W1[(128 + d) * H1_ + n];
    else        w = W1[(128 + d) * H1_ + n];
    __nv_bfloat16 h = __float2bfloat16(w);
    g_B1h[n * 136 + d] = h;
    g_B1l[n * 136 + d] = __float2bfloat16(w - __bfloat162float(h));
}
__global__ void prep_b2(const float* __restrict__ W2) {
    int i = blockIdx.x * blockDim.x + threadIdx.x;   // n*80 + d
    if (i >= H2_ * H1_) return;
    int n = i / H1_, d = i - n * H1_;
    float w = W2[d * H2_ + n];
    __nv_bfloat16 h = __float2bfloat16(w);
    g_B2h[n * 88 + d] = h;
    g_B2l[n * 88 + d] = __float2bfloat16(w - __bfloat162float(h));
}
__global__ void prep_qb(const float* __restrict__ queries,
                        const float* __restrict__ W1,
                        const float* __restrict__ b1) {
    __shared__ float qs[64];
    int b = blockIdx.x, tid = threadIdx.x;
    if (tid < 64) qs[tid] = queries[b * 64 + tid];
    __syncthreads();
    if (tid < H1_) {
        float acc = b1[tid];
        #pragma unroll 8
        for (int d = 0; d < 64; ++d)
            acc += qs[d] * (W1[d * H1_ + tid] + W1[(128 + d) * H1_ + tid]);
        g_qb[b * H1_ + tid] = acc;
    }
}

// ---------------- K1: mma.sync bf16-split GEMM, tile M=64 N=80 K=128 ----------------
// smem bytes: A_hi@0 (64x272=17408), A_lo@17408, B_hi@34816 (80x272=21760), B_lo@56576
#define K1_ALO 17408
#define K1_BHI 34816
#define K1_BLO 56576
#define K1_SMEM 78336

__global__ void __launch_bounds__(256, 2)
k1(const float* __restrict__ keys, const float* __restrict__ queries) {
    extern __shared__ __align__(16) unsigned char smem[];
    uint32_t sb = smem_u32(smem);
    int tid = threadIdx.x, wid = tid >> 5, lid = tid & 31;
    int row0 = blockIdx.x * 64;

    // copy B images (21760 B each = 1360 uint4)
    {
        const uint4* s0 = (const uint4*)g_B1h;
        const uint4* s1 = (const uint4*)g_B1l;
        uint4* d0 = (uint4*)(smem + K1_BHI);
        uint4* d1 = (uint4*)(smem + K1_BLO);
        for (int i = tid; i < 1360; i += 256) { d0[i] = s0[i]; d1[i] = s1[i]; }
    }
    // stage A = [k | q*k], bf16 hi/lo, stride 68 words
    for (int i = tid; i < 64 * 32; i += 256) {
        int r = i >> 5, p = i & 31, dd = 2 * p;
        int grow = row0 + r, b = grow / T_;
        float2 kv = *(const float2*)(keys + (size_t)grow * 64 + dd);
        float2 qv = *(const float2*)(queries + (size_t)b * 64 + dd);
        stash2(smem, smem + K1_ALO, 68, r, p, kv.x, kv.y);
        stash2(smem, smem + K1_ALO, 68, r, p + 32, kv.x * qv.x, kv.y * qv.y);
    }
    __syncthreads();

    int mt = wid & 3, nh = wid >> 2;
    int g = lid >> 2, t = lid & 3;
    float acc[5][4];
    #pragma unroll
    for (int nt = 0; nt < 5; ++nt)
        #pragma unroll
        for (int j = 0; j < 4; ++j) acc[nt][j] = 0.f;

    uint32_t aH = sb + (mt * 16 + g) * 272 + t * 4;
    uint32_t aL = aH + K1_ALO;
    uint32_t bH = sb + K1_BHI + (nh * 40 + g) * 272 + t * 4;
    uint32_t bL = bH + (K1_BLO - K1_BHI);

    #pragma unroll
    for (int ks = 0; ks < 8; ++ks) {
        uint32_t kof = ks * 32;
        uint32_t ah0 = lds32(aH + kof),        ah1 = lds32(aH + 2176 + kof);
        uint32_t ah2 = lds32(aH + 16 + kof),   ah3 = lds32(aH + 2192 + kof);
        uint32_t al0 = lds32(aL + kof),        al1 = lds32(aL + 2176 + kof);
        uint32_t al2 = lds32(aL + 16 + kof),   al3 = lds32(aL + 2192 + kof);
        #pragma unroll
        for (int nt = 0; nt < 5; ++nt) {
            uint32_t bo = nt * 2176 + kof;
            uint32_t bh0 = lds32(bH + bo), bh1 = lds32(bH + bo + 16);
            uint32_t bl0 = lds32(bL + bo), bl1 = lds32(bL + bo + 16);
            mma_bf16(acc[nt], ah0, ah1, ah2, ah3, bh0, bh1);
            mma_bf16(acc[nt], ah0, ah1, ah2, ah3, bl0, bl1);
            mma_bf16(acc[nt], al0, al1, al2, al3, bh0, bh1);
        }
    }
    __syncthreads();

    // stage C into smem [64][81]
    float* smf = (float*)smem;
    #pragma unroll
    for (int nt = 0; nt < 5; ++nt) {
        int col = nh * 40 + nt * 8 + 2 * t;
        int r0 = mt * 16 + g;
        smf[r0 * 81 + col]           = acc[nt][0];
        smf[r0 * 81 + col + 1]       = acc[nt][1];
        smf[(r0 + 8) * 81 + col]     = acc[nt][2];
        smf[(r0 + 8) * 81 + col + 1] = acc[nt][3];
    }
    __syncthreads();

    // add qb, write h1 coalesced, keep v for stats
    for (int i = tid; i < 64 * H1_; i += 256) {
        int r = i / H1_, c = i - r * H1_;
        int grow = row0 + r, b = grow / T_;
        float v = smf[r * 81 + c] + g_qb[b * H1_ + c];
        g_h1[(size_t)grow * H1_ + c] = v;
        smf[r * 81 + c] = v;
    }
    __syncthreads();
    if (tid < H1_) {
        float S = 0.f, SS = 0.f;
        #pragma unroll 8
        for (int r = 0; r < 64; ++r) {
            float v = smf[r * 81 + tid];
            S += v; SS += v * v;
        }
        g_part1[blockIdx.x * (2 * H1_) + tid]       = S;
        g_part1[blockIdx.x * (2 * H1_) + H1_ + tid] = SS;
    }
}

// ---------------- stats ----------------
__global__ void stats1() {
    __shared__ float rs[256], rss[256];
    int h = blockIdx.x, tid = threadIdx.x;
    float S = 0.f, SS = 0.f;
    for (int k = tid; k < NT1; k += 256) {
        S  += g_part1[k * (2 * H1_) + h];
        SS += g_part1[k * (2 * H1_) + H1_ + h];
    }
    rs[tid] = S; rss[tid] = SS;
    __syncthreads();
    for (int st = 128; st > 0; st >>= 1) {
        if (tid < st) { rs[tid] += rs[tid + st]; rss[tid] += rss[tid + st]; }
        __syncthreads();
    }
    if (tid == 0) {
        float mean = rs[0] / (float)NROWS;
        float var  = rss[0] / (float)NROWS - mean * mean;
        g_m1[h] = mean;
        g_r1[h] = rsqrtf(fmaxf(var, 0.f) + 1e-8f);
    }
}
__global__ void stats2() {
    __shared__ float rs[256], rss[256];
    int h = blockIdx.x, tid = threadIdx.x;
    float S = 0.f, SS = 0.f;
    for (int k = tid; k < NT2; k += 256) {
        S  += g_part2[k * (2 * H2_) + h];
        SS += g_part2[k * (2 * H2_) + H2_ + h];
    }
    rs[tid] = S; rss[tid] = SS;
    __syncthreads();
    for (int st = 128; st > 0; st >>= 1) {
        if (tid < st) { rs[tid] += rs[tid + st]; rss[tid] += rss[tid + st]; }
        __syncthreads();
    }
    if (tid == 0) {
        float mean = rs[0] / (float)NROWS;
        float var  = rss[0] / (float)NROWS - mean * mean;
        g_m2[h] = mean;
        g_r2[h] = rsqrtf(fmaxf(var, 0.f) + 1e-8f);
    }
}

// ---------------- K2: dice + mma.sync GEMM, tile M=128 N=40 K=80 ----------------
// smem: A_hi@0 (128x176=22528), A_lo@22528, B_hi@45056 (40x176=7040), B_lo@52096
#define K2_ALO 22528
#define K2_BHI 45056
#define K2_BLO 52096
#define K2_SMEM 59136

__global__ void __launch_bounds__(256, 3)
k2(const float* __restrict__ b2, const float* __restrict__ a1) {
    extern __shared__ __align__(16) unsigned char smem[];
    __shared__ float pm[H1_], pr[H1_], pa[H1_], sb2[H2_];
    uint32_t sb = smem_u32(smem);
    int tid = threadIdx.x, wid = tid >> 5, lid = tid & 31;
    int row0 = blockIdx.x * 128;

    if (tid < H1_) { pm[tid] = g_m1[tid]; pr[tid] = g_r1[tid]; pa[tid] = a1[tid]; }
    if (tid < H2_) sb2[tid] = b2[tid];
    {
        const uint4* s0 = (const uint4*)g_B2h;
        const uint4* s1 = (const uint4*)g_B2l;
        uint4* d0 = (uint4*)(smem + K2_BHI);
        uint4* d1 = (uint4*)(smem + K2_BLO);
        for (int i = tid; i < 440; i += 256) { d0[i] = s0[i]; d1[i] = s1[i]; }
    }
    __syncthreads();

    // stage A = dice(h1), bf16 hi/lo, stride 44 words
    for (int i = tid; i < 128 * 40; i += 256) {
        int r = i / 40, p = i - r * 40, dd = 2 * p;
        float2 xv = *(const float2*)(g_h1 + (size_t)(row0 + r) * H1_ + dd);
        float xn0 = (xv.x - pm[dd]) * pr[dd];
        float xn1 = (xv.y - pm[dd + 1]) * pr[dd + 1];
        float p0 = 1.f / (1.f + __expf(-xn0));
        float p1 = 1.f / (1.f + __expf(-xn1));
        float a0 = pa[dd], a1v = pa[dd + 1];
        float y0 = xv.x * (a0 + p0 * (1.f - a0));
        float y1 = xv.y * (a1v + p1 * (1.f - a1v));
        stash2(smem, smem + K2_ALO, 44, r, p, y0, y1);
    }
    __syncthreads();

    int mt = wid;                       // 8 m-tiles of 16 rows
    int g = lid >> 2, t = lid & 3;
    float acc[5][4];
    #pragma unroll
    for (int nt = 0; nt < 5; ++nt)
        #pragma unroll
        for (int j = 0; j < 4; ++j) acc[nt][j] = 0.f;

    uint32_t aH = sb + (mt * 16 + g) * 176 + t * 4;
    uint32_t aL = aH + K2_ALO;
    uint32_t bH = sb + K2_BHI + g * 176 + t * 4;
    uint32_t bL = bH + (K2_BLO - K2_BHI);

    #pragma unroll
    for (int ks = 0; ks < 5; ++ks) {
        uint32_t kof = ks * 32;
        uint32_t ah0 = lds32(aH + kof),      ah1 = lds32(aH + 1408 + kof);
        uint32_t ah2 = lds32(aH + 16 + kof), ah3 = lds32(aH + 1424 + kof);
        uint32_t al0 = lds32(aL + kof),      al1 = lds32(aL + 1408 + kof);
        uint32_t al2 = lds32(aL + 16 + kof), al3 = lds32(aL + 1424 + kof);
        #pragma unroll
        for (int nt = 0; nt < 5; ++nt) {
            uint32_t bo = nt * 1408 + kof;
            uint32_t bh0 = lds32(bH + bo), bh1 = lds32(bH + bo + 16);
            uint32_t bl0 = lds32(bL + bo), bl1 = lds32(bL + bo + 16);
            mma_bf16(acc[nt], ah0, ah1, ah2, ah3, bh0, bh1);
            mma_bf16(acc[nt], ah0, ah1, ah2, ah3, bl0, bl1);
            mma_bf16(acc[nt], al0, al1, al2, al3, bh0, bh1);
        }
    }
    __syncthreads();

    float* smf = (float*)smem;          // [128][41]
    #pragma unroll
    for (int nt = 0; nt < 5; ++nt) {
        int col = nt * 8 + 2 * t;
        int r0 = mt * 16 + g;
        smf[r0 * 41 + col]           = acc[nt][0];
        smf[r0 * 41 + col + 1]       = acc[nt][1];
        smf[(r0 + 8) * 41 + col]     = acc[nt][2];
        smf[(r0 + 8) * 41 + col + 1] = acc[nt][3];
    }
    __syncthreads();

    for (int i = tid; i < 128 * H2_; i += 256) {
        int r = i / H2_, c = i - r * H2_;
        float v = smf[r * 41 + c] + sb2[c];
        g_h2[(size_t)(row0 + r) * H2_ + c] = v;
        smf[r * 41 + c] = v;
    }
    __syncthreads();
    if (tid < H2_) {
        float S = 0.f, SS = 0.f;
        #pragma unroll 8
        for (int r = 0; r < 128; ++r) {
            float v = smf[r * 41 + tid];
            S += v; SS += v * v;
        }
        g_part2[blockIdx.x * (2 * H2_) + tid]       = S;
        g_part2[blockIdx.x * (2 * H2_) + H2_ + tid] = SS;
    }
}

// ---------------- K3: scores + softmax + weighted key sum ----------------
__global__ void __launch_bounds__(256)
k3(const float* __restrict__ keys, const unsigned char* __restrict__ maskraw,
   const float* __restrict__ W3, const float* __restrict__ b3,
   const float* __restrict__ a2p, float* __restrict__ out) {
    __shared__ float sw[H2_], sm2[H2_], sr2[H2_], sa2[H2_];
    __shared__ float sc[T_];
    __shared__ float red[256];
    __shared__ float osum[256];
    int b = blockIdx.x, tid = threadIdx.x;
    int mode = g_mask_mode;

    if (tid < H2_) {
        sw[tid]  = W3[tid];
        sm2[tid] = g_m2[tid];
        sr2[tid] = g_r2[tid];
        sa2[tid] = a2p[tid];
    }
    __syncthreads();

    if (tid < T_) {
        const float* hp = g_h2 + (size_t)(b * T_ + tid) * H2_;
        float acc = b3[0];
        #pragma unroll
        for (int h = 0; h < H2_; ++h) {
            float x  = hp[h];
            float xn = (x - sm2[h]) * sr2[h];
            float p  = 1.f / (1.f + __expf(-xn));
            float al = sa2[h];
            acc += x * (al + p * (1.f - al)) * sw[h];
        }
        int idx = b * T_ + tid;
        bool mv;
        if (mode == 2)      mv = (((const float*)maskraw)[idx] != 0.0f);
        else if (mode == 1) mv = (((const int*)maskraw)[idx] != 0);
        else                mv = (maskraw[idx] != 0);
        sc[tid] = mv ? acc : PADV;
    }
    __syncthreads();

    red[tid] = (tid < T_) ? sc[tid] : -3.4e38f;
    __syncthreads();
    for (int st = 128; st > 0; st >>= 1) {
        if (tid < st) red[tid] = fmaxf(red[tid], red[tid + st]);
        __syncthreads();
    }
    float m = red[0];
    __syncthreads();

    float e = 0.f;
    if (tid < T_) e = __expf(sc[tid] - m);
    red[tid] = e;
    __syncthreads();
    for (int st = 128; st > 0; st >>= 1) {
        if (tid < st) red[tid] += red[tid + st];
        __syncthreads();
    }
    float inv = 1.0f / red[0];
    if (tid < T_) sc[tid] = e * inv;
    __syncthreads();

    int d = tid & 63, seg = tid >> 6;
    float acc2 = 0.f;
    const float* kp = keys + ((size_t)b * T_ + seg * 50) * 64 + d;
    #pragma unroll 5
    for (int t = 0; t < 50; ++t) acc2 += sc[seg * 50 + t] * kp[(size_t)t * 64];
    osum[tid] = acc2;
    __syncthreads();
    if (tid < 64)
        out[b * 64 + tid] =
            (osum[tid] + osum[64 + tid]) + (osum[128 + tid] + osum[192 + tid]);
}

// ---------------- launch ----------------
extern "C" void kernel_launch(void* const* d_in, const int* in_sizes, int n_in,
                              void* d_out, int out_size) {
    const float* queries = (const float*)d_in[0];
    const float* keys    = (const float*)d_in[1];
    const unsigned char* mask = (const unsigned char*)d_in[2];
    const float* W1 = (const float*)d_in[3];
    const float* b1 = (const float*)d_in[4];
    const float* a1 = (const float*)d_in[5];
    const float* W2 = (const float*)d_in[6];
    const float* b2 = (const float*)d_in[7];
    const float* a2 = (const float*)d_in[8];
    const float* W3 = (const float*)d_in[9];
    const float* b3 = (const float*)d_in[10];
    float* out = (float*)d_out;

    cudaFuncSetAttribute(k1, cudaFuncAttributeMaxDynamicSharedMemorySize, K1_SMEM);
    cudaFuncSetAttribute(k2, cudaFuncAttributeMaxDynamicSharedMemorySize, K2_SMEM);

    detect_mask<<<1, 256>>>(mask);
    prep_b1<<<(H1_ * 128 + 255) / 256, 256>>>(W1);
    prep_b2<<<(H2_ * H1_ + 255) / 256, 256>>>(W2);
    prep_qb<<<B_, 128>>>(queries, W1, b1);
    k1<<<NT1, 256, K1_SMEM>>>(keys, queries);
    stats1<<<H1_, 256>>>();
    k2<<<NT2, 256, K2_SMEM>>>(b2, a1);
    stats2<<<H2_, 256>>>();
    k3<<<B_, 256>>>(keys, mask, W3, b3, a2, out);
}